// round 8
// baseline (speedup 1.0000x reference)
#include <cuda_runtime.h>
#include <cstdint>

#define B_   256
#define P_   4
#define D_   768
#define U_   32
#define IN_  3072

#define BM 128
#define BN 128
#define BK 64
#define NTILES (IN_ / BK)   // 48
#define THREADS 512

// smem: rows of 64 data bytes + 16 pad = 80B stride (ldmatrix conflict-free)
#define ROWS     80
#define PLANE    (128 * ROWS)        // 10240
#define AST_SZ   (2 * PLANE)         // 20480 (hi+lo)
#define BST_SZ   (2 * PLANE)
#define A_STAGES 3
#define OFF_B    (A_STAGES * AST_SZ) // 61440
#define SMEM_TOTAL (A_STAGES * AST_SZ + 2 * BST_SZ)  // 102400

// Pre-quantized A, m-major: [B_][IN_] int8 hi/lo planes
__device__ __align__(16) char g_Ah8[B_ * IN_];
__device__ __align__(16) char g_Al8[B_ * IN_];

// scales: x = (hi*128+lo)/2^11 ; w = (hi*128+lo)/2^19
#define F1 1.52587890625e-05f   // 2^14 / 2^30
#define F2 1.1920928955078125e-07f  // 2^7 / 2^30

__device__ __forceinline__ uint32_t smem_u32(const void* p) {
    uint32_t a;
    asm("{ .reg .u64 t; cvta.to.shared.u64 t, %1; cvt.u32.u64 %0, t; }" : "=r"(a) : "l"(p));
    return a;
}
#define CP_ASYNC16(dst, src) \
    asm volatile("cp.async.cg.shared.global [%0], [%1], 16;" :: "r"(dst), "l"(src))
#define CP_COMMIT() asm volatile("cp.async.commit_group;" ::: "memory")
#define CP_WAIT1()  asm volatile("cp.async.wait_group 1;" ::: "memory")

#define LDSM_X4(r, addr) \
    asm volatile("ldmatrix.sync.aligned.m8n8.x4.shared.b16 {%0,%1,%2,%3}, [%4];" \
        : "=r"((r)[0]), "=r"((r)[1]), "=r"((r)[2]), "=r"((r)[3]) : "r"(addr))

#define MMA_S8(d, a, b0_, b1_) \
    asm volatile("mma.sync.aligned.m16n8k32.row.col.s32.s8.s8.s32 " \
        "{%0,%1,%2,%3}, {%4,%5,%6,%7}, {%8,%9}, {%0,%1,%2,%3};" \
        : "+r"((d)[0]), "+r"((d)[1]), "+r"((d)[2]), "+r"((d)[3]) \
        : "r"((a)[0]), "r"((a)[1]), "r"((a)[2]), "r"((a)[3]), "r"(b0_), "r"(b1_))

// q = clamp(round(x*scale), +-16255); hi = (q+64)>>7 in [-127,127]; lo = q-128*hi in [-64,63]
__device__ __forceinline__ void quant15(float x, float scale, int& hi, int& lo) {
    int q = __float2int_rn(x * scale);
    q = max(-16255, min(16255, q));
    hi = (q + 64) >> 7;
    lo = q - (hi << 7);
}
__device__ __forceinline__ uint32_t packb(int b0, int b1, int b2, int b3) {
    return (uint32_t)(b0 & 0xFF) | ((uint32_t)(b1 & 0xFF) << 8) |
           ((uint32_t)(b2 & 0xFF) << 16) | ((uint32_t)b3 << 24);
}

// ---------------- A quantization pre-pass ----------------
__global__ void coldprompt_quantA(const float* __restrict__ A)
{
    const int t = blockIdx.x * blockDim.x + threadIdx.x;   // 196608 quads
    if (t >= (B_ * IN_) / 4) return;
    float4 v = ((const float4*)A)[t];
    int h0, l0, h1, l1, h2, l2, h3, l3;
    quant15(v.x, 2048.0f, h0, l0);
    quant15(v.y, 2048.0f, h1, l1);
    quant15(v.z, 2048.0f, h2, l2);
    quant15(v.w, 2048.0f, h3, l3);
    ((uint32_t*)g_Ah8)[t] = packb(h0, h1, h2, h3);
    ((uint32_t*)g_Al8)[t] = packb(l0, l1, l2, l3);
}

// ---------------- mean ----------------
__global__ void coldprompt_mean(const float* __restrict__ w, float* __restrict__ out)
{
    const int n4 = (B_ * D_) / 4;
    int i = blockIdx.x * blockDim.x + threadIdx.x;
    if (i >= n4) return;
    const int dpr = D_ / 4;
    const int b  = i / dpr;
    const int d4 = i % dpr;
    const float4* wp = (const float4*)w;
    float4 s = make_float4(0.f, 0.f, 0.f, 0.f);
    #pragma unroll
    for (int p = 0; p < P_; p++) {
        float4 v = wp[(size_t)(b * P_ + p) * dpr + d4];
        s.x += v.x; s.y += v.y; s.z += v.z; s.w += v.w;
    }
    s.x *= 0.25f; s.y *= 0.25f; s.z *= 0.25f; s.w *= 0.25f;
    ((float4*)out)[i] = s;
}

// ---------------- Main GEMM: IMMA s8 k32, 512 threads ----------------
__global__ void __launch_bounds__(THREADS, 1)
coldprompt_imma_gemm(const float* __restrict__ W,     // [32, 3072, 768]
                     const float* __restrict__ bias,  // [32, 768]
                     float* __restrict__ C)           // [32*256, 768]
{
    extern __shared__ char smem[];
    const uint32_t sb = smem_u32(smem);

    const int tid  = threadIdx.x;
    const int wid  = tid >> 5;
    const int lane = tid & 31;
    const int u    = blockIdx.z;
    const int m0   = blockIdx.y * BM;
    const int n0   = blockIdx.x * BN;

    const int wm = (wid & 3) * 32;    // 4 m-warps of 32
    const int wn = (wid >> 2) * 32;   // 4 n-warps of 32

    const float* __restrict__ Wbase = W + (size_t)u * IN_ * D_ + n0;

    // A cp.async mapping: 1024 16B-chunks (2 planes), 2 per thread
    // B build mapping: n = tid&127, k-block bg = tid>>7 (16 k each)
    const int bn = tid & 127;
    const int bg = tid >> 7;
    const int b_kbs = (bg + (bn >> 3)) & 3;   // swizzled 16B block

    int acc1[2][4][4], acc2[2][4][4];
    #pragma unroll
    for (int i = 0; i < 2; i++)
        #pragma unroll
        for (int j = 0; j < 4; j++)
            #pragma unroll
            for (int r = 0; r < 4; r++) { acc1[i][j][r] = 0; acc2[i][j][r] = 0; }

    float breg[16];

    auto ISSUE_A = [&](int it) {
        const uint32_t st = sb + (it % A_STAGES) * AST_SZ;
        const int k0 = it * BK;
        #pragma unroll
        for (int c = 0; c < 2; ++c) {
            const int idx = tid + 512 * c;      // 0..1023
            const int pl  = idx >> 9;           // plane
            const int r   = idx & 511;
            const int m   = r >> 2;
            const int q   = r & 3;
            const char* src = (pl ? g_Al8 : g_Ah8) +
                              (size_t)(m0 + m) * IN_ + k0 + q * 16;
            CP_ASYNC16(st + pl * PLANE + m * ROWS + q * 16, src);
        }
    };
    auto LDG_B = [&](int it, float (&f)[16]) {
        const int kbase = it * BK + bg * 16;
        #pragma unroll
        for (int j = 0; j < 16; ++j)
            f[j] = Wbase[(size_t)(kbase + j) * D_ + bn];
    };
    auto STS_B = [&](int it, const float (&f)[16]) {
        char* st = smem + OFF_B + (it & 1) * BST_SZ;
        char* base = st + bn * ROWS + b_kbs * 16;
        #pragma unroll
        for (int grp = 0; grp < 4; ++grp) {
            int h0, l0, h1, l1, h2, l2, h3, l3;
            quant15(f[grp * 4 + 0], 524288.0f, h0, l0);
            quant15(f[grp * 4 + 1], 524288.0f, h1, l1);
            quant15(f[grp * 4 + 2], 524288.0f, h2, l2);
            quant15(f[grp * 4 + 3], 524288.0f, h3, l3);
            *(uint32_t*)(base + grp * 4)         = packb(h0, h1, h2, h3);
            *(uint32_t*)(base + PLANE + grp * 4) = packb(l0, l1, l2, l3);
        }
    };

    // ldmatrix lane address components
    const int a_r  = lane & 7;
    const int a_m8 = ((lane >> 3) & 1) * 8;
    const int a_kb = lane >> 4;                 // 0/1
    const int b_r  = lane & 7;
    const int b_n8 = ((lane >> 4) & 1) * 8;
    const int b_kb = (lane >> 3) & 1;

    auto COMPUTE = [&](int it) {
        const uint32_t sa = sb + (it % A_STAGES) * AST_SZ;
        const uint32_t sB = sb + OFF_B + (it & 1) * BST_SZ;
        #pragma unroll
        for (int ks = 0; ks < 2; ++ks) {
            // A frags: x4 = (m0-7,kb0),(m8-15,kb0),(m0-7,kb1),(m8-15,kb1)
            uint32_t ah[2][4], al[2][4];
            #pragma unroll
            for (int mt = 0; mt < 2; ++mt) {
                const uint32_t ao =
                    (wm + mt * 16 + a_m8 + a_r) * ROWS + (ks * 2 + a_kb) * 16;
                LDSM_X4(ah[mt], sa + ao);
                LDSM_X4(al[mt], sa + PLANE + ao);
            }
            // B frags: x4 = (n0-7,kb0),(n0-7,kb1),(n8-15,kb0),(n8-15,kb1)
            uint32_t bh[8], bl[8];
            #pragma unroll
            for (int ntp = 0; ntp < 2; ++ntp) {
                const int nrow = wn + ntp * 16 + b_n8 + b_r;
                const int kb   = ks * 2 + b_kb;
                const uint32_t bo = nrow * ROWS + (((kb + (nrow >> 3)) & 3) << 4);
                LDSM_X4(&bh[ntp * 4], sB + bo);
                LDSM_X4(&bl[ntp * 4], sB + PLANE + bo);
            }
            #pragma unroll
            for (int mt = 0; mt < 2; ++mt)
                #pragma unroll
                for (int nt = 0; nt < 4; ++nt) {
                    MMA_S8(acc1[mt][nt], ah[mt], bh[nt * 2], bh[nt * 2 + 1]);
                    MMA_S8(acc2[mt][nt], ah[mt], bl[nt * 2], bl[nt * 2 + 1]);
                    MMA_S8(acc2[mt][nt], al[mt], bh[nt * 2], bh[nt * 2 + 1]);
                }
        }
    };

    // ---- prologue ----
    ISSUE_A(0); CP_COMMIT();
    ISSUE_A(1); CP_COMMIT();
    LDG_B(0, breg);
    STS_B(0, breg);
    LDG_B(1, breg);

    // ---- mainloop: one sync per tile ----
    #pragma unroll 1
    for (int it = 0; it < NTILES; ++it) {
        CP_WAIT1();            // A(it) landed
        __syncthreads();       // A(it)+B(it) visible; all warps past COMPUTE(it-1)
        if (it + 1 < NTILES) STS_B(it + 1, breg);
        if (it + 2 < NTILES) {
            LDG_B(it + 2, breg);
            ISSUE_A(it + 2);
        }
        CP_COMMIT();
        COMPUTE(it);
    }

    // ---- epilogue ----
    const int g  = lane >> 2;
    const int tq = lane & 3;
    #pragma unroll
    for (int mt = 0; mt < 2; ++mt) {
        #pragma unroll
        for (int nt = 0; nt < 4; ++nt) {
            const int row0 = m0 + wm + mt * 16 + g;
            const int col  = n0 + wn + nt * 8 + tq * 2;
            const float2 bv = *(const float2*)(bias + (size_t)u * D_ + col);
            float* c0 = C + ((size_t)u * B_ + row0) * D_ + col;
            float* c1 = c0 + (size_t)8 * D_;
            float2 o0, o1;
            o0.x = F1 * (float)acc1[mt][nt][0] + F2 * (float)acc2[mt][nt][0] + bv.x;
            o0.y = F1 * (float)acc1[mt][nt][1] + F2 * (float)acc2[mt][nt][1] + bv.y;
            o1.x = F1 * (float)acc1[mt][nt][2] + F2 * (float)acc2[mt][nt][2] + bv.x;
            o1.y = F1 * (float)acc1[mt][nt][3] + F2 * (float)acc2[mt][nt][3] + bv.y;
            *(float2*)c0 = o0;
            *(float2*)c1 = o1;
        }
    }
}

extern "C" void kernel_launch(void* const* d_in, const int* in_sizes, int n_in,
                              void* d_out, int out_size)
{
    const float* weight = (const float*)d_in[0];
    const float* W_spec = (const float*)d_in[1];
    const float* b_spec = (const float*)d_in[2];
    float* out = (float*)d_out;

    cudaFuncSetAttribute(coldprompt_imma_gemm,
                         cudaFuncAttributeMaxDynamicSharedMemorySize, SMEM_TOTAL);

    const int nq = (B_ * IN_) / 4;
    coldprompt_quantA<<<(nq + 255) / 256, 256>>>(weight);

    const int n4 = (B_ * D_) / 4;
    coldprompt_mean<<<(n4 + 255) / 256, 256>>>(weight, out + (size_t)U_ * B_ * D_);

    dim3 grid(D_ / BN, B_ / BM, U_);   // (6, 2, 32)
    coldprompt_imma_gemm<<<grid, THREADS, SMEM_TOTAL>>>(W_spec, b_spec, out);
}

// round 9
// speedup vs baseline: 2.8328x; 2.8328x over previous
#include <cuda_runtime.h>
#include <cuda_bf16.h>
#include <cstdint>

#define B_   256
#define P_   4
#define D_   768
#define U_   32
#define IN_  3072

#define BM 128
#define BN 64
#define BK 32
#define NTILES (IN_ / BK)   // 96
#define THREADS 256

// smem strides (bytes): A rows 272 (proven), B rows 144 (64 bf16 + 8 pad)
#define ROW_A   272
#define ROW_Bb  144
#define A_PLANE (32 * ROW_A)          // 8704
#define B_PLANE (32 * ROW_Bb)         // 4608
#define ST_AH   0
#define ST_AL   A_PLANE
#define ST_BH   (2 * A_PLANE)
#define ST_BL   (2 * A_PLANE + B_PLANE)
#define STAGE_SZ (2 * A_PLANE + 2 * B_PLANE)   // 26624
#define SMEM_TOTAL (2 * STAGE_SZ)              // 53248  -> 2 CTAs/SM

// Pre-converted A, K-major: [IN_][B_] bf16 hi/lo planes (L2-resident, reused 384x)
__device__ __align__(16) __nv_bfloat16 g_Ahi[IN_ * B_];
__device__ __align__(16) __nv_bfloat16 g_Alo[IN_ * B_];

__device__ __forceinline__ uint32_t smem_u32(const void* p) {
    uint32_t a;
    asm("{ .reg .u64 t; cvta.to.shared.u64 t, %1; cvt.u32.u64 %0, t; }" : "=r"(a) : "l"(p));
    return a;
}
#define LDSM_X4T(r, addr) \
    asm volatile("ldmatrix.sync.aligned.m8n8.x4.trans.shared.b16 {%0,%1,%2,%3}, [%4];" \
        : "=r"((r)[0]), "=r"((r)[1]), "=r"((r)[2]), "=r"((r)[3]) : "r"(addr))
#define MMA16816(d, a, b0, b1) \
    asm volatile("mma.sync.aligned.m16n8k16.row.col.f32.bf16.bf16.f32 " \
        "{%0,%1,%2,%3}, {%4,%5,%6,%7}, {%8,%9}, {%0,%1,%2,%3};" \
        : "+f"((d)[0]), "+f"((d)[1]), "+f"((d)[2]), "+f"((d)[3]) \
        : "r"((a)[0]), "r"((a)[1]), "r"((a)[2]), "r"((a)[3]), "r"(b0), "r"(b1))

// hi = [bf16(y):bf16(x)], lo = residual pair
__device__ __forceinline__ void cvt_hilo2(float x, float y, uint32_t& hi, uint32_t& lo) {
    asm("cvt.rn.bf16x2.f32 %0, %1, %2;" : "=r"(hi) : "f"(y), "f"(x));
    float xh = __uint_as_float(hi << 16);
    float yh = __uint_as_float(hi & 0xffff0000u);
    float dx = x - xh;
    float dy = y - yh;
    asm("cvt.rn.bf16x2.f32 %0, %1, %2;" : "=r"(lo) : "f"(dy), "f"(dx));
}

// ---------------- Fused pre-pass: A -> K-major bf16 hi/lo planes + mean ----------------
__global__ void coldprompt_prep_mean(const float* __restrict__ A, float* __restrict__ mean_out)
{
    __shared__ float T[32][33];
    const int tid = threadIdx.x;
    const int b0  = blockIdx.x * 32;
    const int d0  = blockIdx.y * 32;

    const int bb  = tid >> 3;
    const int dd4 = (tid & 7) * 4;
    const int kk  = tid >> 3;
    const int bb4 = (tid & 7) * 4;

    float4 s = make_float4(0.f, 0.f, 0.f, 0.f);

    #pragma unroll
    for (int p = 0; p < P_; ++p) {
        float4 v = *(const float4*)(A + ((size_t)(b0 + bb) * P_ + p) * D_ + d0 + dd4);
        s.x += v.x; s.y += v.y; s.z += v.z; s.w += v.w;
        T[dd4 + 0][bb] = v.x;
        T[dd4 + 1][bb] = v.y;
        T[dd4 + 2][bb] = v.z;
        T[dd4 + 3][bb] = v.w;
        __syncthreads();
        {
            float x0 = T[kk][bb4 + 0], x1 = T[kk][bb4 + 1];
            float x2 = T[kk][bb4 + 2], x3 = T[kk][bb4 + 3];
            uint32_t h0, l0, h1, l1;
            cvt_hilo2(x0, x1, h0, l0);
            cvt_hilo2(x2, x3, h1, l1);
            const size_t o = (size_t)(p * D_ + d0 + kk) * B_ + b0 + bb4;
            *(uint2*)(g_Ahi + o) = make_uint2(h0, h1);
            *(uint2*)(g_Alo + o) = make_uint2(l0, l1);
        }
        __syncthreads();
    }
    s.x *= 0.25f; s.y *= 0.25f; s.z *= 0.25f; s.w *= 0.25f;
    *(float4*)(mean_out + (size_t)(b0 + bb) * D_ + d0 + dd4) = s;
}

// ---------------- Main GEMM: R5 structure, BN=64, 2 CTAs/SM ----------------
__global__ void __launch_bounds__(THREADS, 2)
coldprompt_mma_gemm(const float* __restrict__ W,     // [32, 3072, 768]
                    const float* __restrict__ bias,  // [32, 768]
                    float* __restrict__ C)           // [32*256, 768]
{
    extern __shared__ char smem[];
    const uint32_t sb = smem_u32(smem);

    const int tid  = threadIdx.x;
    const int wid  = tid >> 5;
    const int lane = tid & 31;
    const int u    = blockIdx.z;
    const int m0   = blockIdx.y * BM;
    const int n0   = blockIdx.x * BN;

    const int wm = (wid & 3) * 32;    // 4 m-warps of 32
    const int wn = (wid >> 2) * 32;   // 2 n-warps of 32

    const float* __restrict__ Wbase = W + (size_t)u * IN_ * D_ + n0;

    // A copy mapping (R5): per plane 2 chunks of 16B
    const int a_row0 = tid >> 4;            // k-row 0..15 (chunk0), +16 (chunk1)
    const int a_c8   = (tid & 15) * 8;      // m elem offset (16B)
    // B load mapping: 2 float4 per thread (32k x 64n = 2048 floats)
    const int b_kr0 = tid >> 4;             // 0..15 (+16 for c=1)
    const int b_n4  = (tid & 15) * 4;

    float acc[2][4][4];
    #pragma unroll
    for (int i = 0; i < 2; i++)
        #pragma unroll
        for (int j = 0; j < 4; j++) {
            acc[i][j][0] = 0.f; acc[i][j][1] = 0.f;
            acc[i][j][2] = 0.f; acc[i][j][3] = 0.f;
        }

    uint4  areg_h[2], areg_l[2];
    float4 breg[2];

    auto LOAD = [&](int it) {
        const int k0 = it * BK;
        #pragma unroll
        for (int c = 0; c < 2; ++c) {
            const int kr = a_row0 + c * 16;
            const size_t o = (size_t)(k0 + kr) * B_ + m0 + a_c8;
            areg_h[c] = *(const uint4*)(g_Ahi + o);
            areg_l[c] = *(const uint4*)(g_Alo + o);
        }
        #pragma unroll
        for (int c = 0; c < 2; ++c) {
            const int kr = b_kr0 + c * 16;
            breg[c] = *(const float4*)(Wbase + (size_t)(k0 + kr) * D_ + b_n4);
        }
    };

    auto STORE = [&](int s) {
        char* st = smem + s * STAGE_SZ;
        #pragma unroll
        for (int c = 0; c < 2; ++c) {
            const int kr = a_row0 + c * 16;
            char* p = st + kr * ROW_A + a_c8 * 2;
            *(uint4*)(p + ST_AH) = areg_h[c];
            *(uint4*)(p + ST_AL) = areg_l[c];
        }
        #pragma unroll
        for (int c = 0; c < 2; ++c) {
            const int kr = b_kr0 + c * 16;
            uint32_t h0, l0, h1, l1;
            cvt_hilo2(breg[c].x, breg[c].y, h0, l0);
            cvt_hilo2(breg[c].z, breg[c].w, h1, l1);
            char* p = st + kr * ROW_Bb + b_n4 * 2;
            *(uint2*)(p + ST_BH) = make_uint2(h0, h1);
            *(uint2*)(p + ST_BL) = make_uint2(l0, l1);
        }
    };

    // ldmatrix lane address components (proven mapping)
    const uint32_t a_krow = (lane & 7) + ((lane >> 4) & 1) * 8;
    const uint32_t a_mcol = ((lane >> 3) & 1) * 8;
    const uint32_t b_krow = (lane & 7) + ((lane >> 3) & 1) * 8;
    const uint32_t b_ncol = (lane >> 4) * 8;

    auto COMPUTE = [&](int s) {
        const uint32_t st = sb + s * STAGE_SZ;
        #pragma unroll
        for (int ks = 0; ks < 2; ++ks) {
            uint32_t a_hi[2][4], a_lo[2][4];
            #pragma unroll
            for (int mt = 0; mt < 2; ++mt) {
                const uint32_t ao =
                    (ks * 16 + a_krow) * ROW_A + (wm + mt * 16 + a_mcol) * 2;
                LDSM_X4T(a_hi[mt], st + ST_AH + ao);
                LDSM_X4T(a_lo[mt], st + ST_AL + ao);
            }
            uint32_t b_hi[8], b_lo[8];
            #pragma unroll
            for (int nt2 = 0; nt2 < 2; ++nt2) {
                const uint32_t bo =
                    (ks * 16 + b_krow) * ROW_Bb + (wn + nt2 * 16 + b_ncol) * 2;
                LDSM_X4T(&b_hi[nt2 * 4], st + ST_BH + bo);
                LDSM_X4T(&b_lo[nt2 * 4], st + ST_BL + bo);
            }
            #pragma unroll
            for (int mt = 0; mt < 2; ++mt)
                #pragma unroll
                for (int nt = 0; nt < 4; ++nt) {
                    MMA16816(acc[mt][nt], a_hi[mt], b_hi[nt * 2], b_hi[nt * 2 + 1]);
                    MMA16816(acc[mt][nt], a_hi[mt], b_lo[nt * 2], b_lo[nt * 2 + 1]);
                    MMA16816(acc[mt][nt], a_lo[mt], b_hi[nt * 2], b_hi[nt * 2 + 1]);
                }
        }
    };

    // ---- pipeline (R5 structure, proven) ----
    LOAD(0);
    STORE(0);
    __syncthreads();

    #pragma unroll 1
    for (int it = 0; it < NTILES; ++it) {
        if (it + 1 < NTILES) LOAD(it + 1);
        COMPUTE(it & 1);
        if (it + 1 < NTILES) {
            __syncthreads();
            STORE((it + 1) & 1);
            __syncthreads();
        }
    }

    // ---- epilogue ----
    const int g  = lane >> 2;
    const int tq = lane & 3;
    #pragma unroll
    for (int mt = 0; mt < 2; ++mt) {
        #pragma unroll
        for (int nt = 0; nt < 4; ++nt) {
            const int row0 = m0 + wm + mt * 16 + g;
            const int col  = n0 + wn + nt * 8 + tq * 2;
            const float2 bv = *(const float2*)(bias + (size_t)u * D_ + col);
            float* c0 = C + ((size_t)u * B_ + row0) * D_ + col;
            float* c1 = c0 + (size_t)8 * D_;
            float2 o0, o1;
            o0.x = acc[mt][nt][0] + bv.x;
            o0.y = acc[mt][nt][1] + bv.y;
            o1.x = acc[mt][nt][2] + bv.x;
            o1.y = acc[mt][nt][3] + bv.y;
            *(float2*)c0 = o0;
            *(float2*)c1 = o1;
        }
    }
}

extern "C" void kernel_launch(void* const* d_in, const int* in_sizes, int n_in,
                              void* d_out, int out_size)
{
    const float* weight = (const float*)d_in[0];
    const float* W_spec = (const float*)d_in[1];
    const float* b_spec = (const float*)d_in[2];
    float* out = (float*)d_out;

    cudaFuncSetAttribute(coldprompt_mma_gemm,
                         cudaFuncAttributeMaxDynamicSharedMemorySize, SMEM_TOTAL);

    dim3 pgrid(B_ / 32, D_ / 32);   // (8, 24)
    coldprompt_prep_mean<<<pgrid, 256>>>(weight, out + (size_t)U_ * B_ * D_);

    dim3 grid(D_ / BN, B_ / BM, U_);   // (12, 2, 32) = 768 CTAs, 2/SM
    coldprompt_mma_gemm<<<grid, THREADS, SMEM_TOTAL>>>(W_spec, b_spec, out);
}